// round 7
// baseline (speedup 1.0000x reference)
#include <cuda_runtime.h>
#include <math.h>

#define BPB 288            // blocks per batch; 1152 CTAs total
#define THREADS 256
#define NBATCH 4
#define NELEM (192*192*192)        // 7,077,888 per batch
#define NVEC  (NELEM/4)            // 1,769,472 float4 per batch
#define STRIDE (BPB * THREADS)
#define NITER (NVEC / STRIDE)      // exactly 24, no tail

__device__ float g_partials[NBATCH * BPB * 5];
__device__ unsigned int g_ticket[NBATCH];   // zero-init; reset by last block each run

__device__ __forceinline__ float warp_sum(float v) {
    #pragma unroll
    for (int o = 16; o > 0; o >>= 1)
        v += __shfl_xor_sync(0xFFFFFFFFu, v, o);
    return v;
}

__global__ __launch_bounds__(THREADS, 6)   // <=40 regs: room for 4 live float4s
void ncc_fused(const float4* __restrict__ J4,   // y_pred
               const float4* __restrict__ I4,   // y_true
               float* __restrict__ out)
{
    const int b = blockIdx.y;
    const float4* __restrict__ Ib = I4 + (size_t)b * NVEC;
    const float4* __restrict__ Jb = J4 + (size_t)b * NVEC;

    float sI = 0.f, sJ = 0.f, sII = 0.f, sJJ = 0.f, sIJ = 0.f;

    const int base = blockIdx.x * THREADS + threadIdx.x;
    // NITER = 24 -> 12 double-iterations; 4 independent LDG.128 per body
    #pragma unroll 2
    for (int k = 0; k < NITER; k += 2) {
        const int i0 = base + k * STRIDE;
        const int i1 = i0 + STRIDE;
        // batch all 4 loads before any consumption
        float4 a0 = Ib[i0];
        float4 c0 = Jb[i0];
        float4 a1 = Ib[i1];
        float4 c1 = Jb[i1];

        sI  += a0.x + a0.y + a0.z + a0.w;
        sJ  += c0.x + c0.y + c0.z + c0.w;
        sII += a0.x*a0.x + a0.y*a0.y + a0.z*a0.z + a0.w*a0.w;
        sJJ += c0.x*c0.x + c0.y*c0.y + c0.z*c0.z + c0.w*c0.w;
        sIJ += a0.x*c0.x + a0.y*c0.y + a0.z*c0.z + a0.w*c0.w;

        sI  += a1.x + a1.y + a1.z + a1.w;
        sJ  += c1.x + c1.y + c1.z + c1.w;
        sII += a1.x*a1.x + a1.y*a1.y + a1.z*a1.z + a1.w*a1.w;
        sJJ += c1.x*c1.x + c1.y*c1.y + c1.z*c1.z + c1.w*c1.w;
        sIJ += a1.x*c1.x + a1.y*c1.y + a1.z*c1.z + a1.w*c1.w;
    }

    // intra-warp reduce
    sI  = warp_sum(sI);
    sJ  = warp_sum(sJ);
    sII = warp_sum(sII);
    sJJ = warp_sum(sJJ);
    sIJ = warp_sum(sIJ);

    __shared__ float sm[5][THREADS / 32];
    const int lane = threadIdx.x & 31;
    const int wid  = threadIdx.x >> 5;
    if (lane == 0) {
        sm[0][wid] = sI;  sm[1][wid] = sJ;  sm[2][wid] = sII;
        sm[3][wid] = sJJ; sm[4][wid] = sIJ;
    }
    __syncthreads();

    __shared__ bool isLast;
    if (wid == 0) {
        const int nw = THREADS / 32;
        float v0 = (lane < nw) ? sm[0][lane] : 0.f;
        float v1 = (lane < nw) ? sm[1][lane] : 0.f;
        float v2 = (lane < nw) ? sm[2][lane] : 0.f;
        float v3 = (lane < nw) ? sm[3][lane] : 0.f;
        float v4 = (lane < nw) ? sm[4][lane] : 0.f;
        v0 = warp_sum(v0); v1 = warp_sum(v1); v2 = warp_sum(v2);
        v3 = warp_sum(v3); v4 = warp_sum(v4);
        if (lane == 0) {
            float* p = &g_partials[(b * BPB + blockIdx.x) * 5];
            p[0] = v0; p[1] = v1; p[2] = v2; p[3] = v3; p[4] = v4;
            __threadfence();
            unsigned int t = atomicAdd(&g_ticket[b], 1u);
            isLast = (t == BPB - 1);
        }
    }
    __syncthreads();

    if (!isLast) return;

    // ---- last block for this batch: final reduce over BPB partials ----
    float tI = 0.f, tJ = 0.f, tII = 0.f, tJJ = 0.f, tIJ = 0.f;
    for (int i = threadIdx.x; i < BPB; i += THREADS) {
        const float* p = &g_partials[(b * BPB + i) * 5];
        tI += p[0]; tJ += p[1]; tII += p[2]; tJJ += p[3]; tIJ += p[4];
    }
    tI  = warp_sum(tI);
    tJ  = warp_sum(tJ);
    tII = warp_sum(tII);
    tJJ = warp_sum(tJJ);
    tIJ = warp_sum(tIJ);

    __syncthreads();   // sm[][] reuse
    if (lane == 0) {
        sm[0][wid] = tI;  sm[1][wid] = tJ;  sm[2][wid] = tII;
        sm[3][wid] = tJJ; sm[4][wid] = tIJ;
    }
    __syncthreads();

    if (threadIdx.x == 0) {
        const int nw = THREADS / 32;
        float fI = 0.f, fJ = 0.f, fII = 0.f, fJJ = 0.f, fIJ = 0.f;
        for (int w = 0; w < nw; w++) {
            fI += sm[0][w]; fJ += sm[1][w]; fII += sm[2][w];
            fJJ += sm[3][w]; fIJ += sm[4][w];
        }
        const float n = (float)NELEM;
        float cross = fIJ - fI * fJ / n;
        float Ivar  = fII - fI * fI / n;
        float Jvar  = fJJ - fJ * fJ / n;
        out[b] = cross / (sqrtf(Ivar) * sqrtf(Jvar) + 1e-5f);
        g_ticket[b] = 0u;    // reset for next graph replay
    }
}

extern "C" void kernel_launch(void* const* d_in, const int* in_sizes, int n_in,
                              void* d_out, int out_size)
{
    const float4* y_pred = (const float4*)d_in[0];  // Ji
    const float4* y_true = (const float4*)d_in[1];  // Ii
    float* out = (float*)d_out;

    dim3 grid(BPB, NBATCH);
    ncc_fused<<<grid, THREADS>>>(y_pred, y_true, out);
}